// round 15
// baseline (speedup 1.0000x reference)
#include <cuda_runtime.h>
#include <cstdint>

// Problem constants
#define T_STEPS 512
#define BATCH   8
#define DDIM    512
#define NDIM    64
#define M_ROWS  (T_STEPS * BATCH)   // 4096 rows for the projection GEMM
#define E_COLS  1152                // 512 (k) + 512 (q) + 64 (wx) + 64 (alpha)

typedef unsigned long long u64;

// ---------------------------------------------------------------------------
// Scratch (no cudaMalloc allowed)
// ---------------------------------------------------------------------------
__device__ float g_k[M_ROWS * DDIM];      // k_all   [T*B, D]
__device__ float g_q[M_ROWS * DDIM];      // q_all   [T*B, D]
__device__ float g_wx[M_ROWS * NDIM];     // Wx_all  [T*B, N]
__device__ float g_alpha[M_ROWS * NDIM];  // sigmoid(ax_all) [T*B, N]
__device__ float g_kq[M_ROWS];            // k_t . q_t
__device__ float g_kk2[M_ROWS];           // k_{t-1} . k_t   (0 at t=0)
__device__ float g_kqp[M_ROWS];           // k_{t-1} . q_t   (0 at t=0)

// ---------------------------------------------------------------------------
// Fast math helpers
// ---------------------------------------------------------------------------
__device__ __forceinline__ float tanh_f(float x) {
    float e = __expf(2.0f * x);
    return 1.0f - __fdividef(2.0f, e + 1.0f);
}
__device__ __forceinline__ float sigmoid_f(float x) {
    float e = __expf(-x);
    return __fdividef(1.0f, 1.0f + e);
}

// ---------------------------------------------------------------------------
// Cluster / mbarrier helpers
// ---------------------------------------------------------------------------
__device__ __forceinline__ uint32_t mapa_sh(uint32_t addr, int rank) {
    uint32_t d;
    asm("mapa.shared::cluster.u32 %0, %1, %2;" : "=r"(d) : "r"(addr), "r"(rank));
    return d;
}
__device__ __forceinline__ void mbar_init(uint32_t addr, uint32_t cnt) {
    asm volatile("mbarrier.init.shared.b64 [%0], %1;" :: "r"(addr), "r"(cnt) : "memory");
}
__device__ __forceinline__ void mbar_expect_tx(uint32_t addr, uint32_t bytes) {
    asm volatile("mbarrier.arrive.expect_tx.shared.b64 _, [%0], %1;"
                 :: "r"(addr), "r"(bytes) : "memory");
}
__device__ __forceinline__ void mbar_wait_parity(uint32_t addr, uint32_t parity) {
    asm volatile(
        "{\n\t"
        ".reg .pred P;\n\t"
        "WAIT_%=:\n\t"
        "mbarrier.try_wait.parity.acquire.cluster.shared::cta.b64 P, [%0], %1, 0x989680;\n\t"
        "@!P bra WAIT_%=;\n\t"
        "}"
        :: "r"(addr), "r"(parity) : "memory");
}
// Bulk SMEM->peer-SMEM copy with tx-completion on the TARGET CTA's mbarrier.
__device__ __forceinline__ void bulk_s2s(uint32_t rdst, uint32_t lsrc,
                                         uint32_t bytes, uint32_t rmbar) {
    asm volatile(
        "cp.async.bulk.shared::cluster.shared::cta.mbarrier::complete_tx::bytes "
        "[%0], [%1], %2, [%3];"
        :: "r"(rdst), "r"(lsrc), "r"(bytes), "r"(rmbar) : "memory");
}
__device__ __forceinline__ void fence_proxy_async_cta() {
    asm volatile("fence.proxy.async.shared::cta;" ::: "memory");
}

// ---------------------------------------------------------------------------
// Kernel 1: fused projection GEMM (unchanged; ~125 us)
// ---------------------------------------------------------------------------
__global__ void __launch_bounds__(256)
proj_gemm_kernel(const float* __restrict__ x,
                 const float* __restrict__ Wk,
                 const float* __restrict__ Wq,
                 const float* __restrict__ Wx,
                 const float* __restrict__ Wa,
                 const float* __restrict__ ba)
{
    __shared__ float As[32][132];
    __shared__ float Bs[32][68];

    const int tid = threadIdx.x;
    const int m0 = blockIdx.x * 128;
    const int etile = blockIdx.y;

    const float* Wp;
    int erow0, mode;
    if (etile < 8)        { Wp = Wk; erow0 = etile * 64;        mode = 0; }
    else if (etile < 16)  { Wp = Wq; erow0 = (etile - 8) * 64;  mode = 1; }
    else if (etile == 16) { Wp = Wx; erow0 = 0;                 mode = 2; }
    else                  { Wp = Wa; erow0 = 0;                 mode = 3; }

    const int tx = tid & 15;
    const int ty = tid >> 4;

    float acc[8][4];
#pragma unroll
    for (int i = 0; i < 8; i++)
#pragma unroll
        for (int j = 0; j < 4; j++) acc[i][j] = 0.0f;

    const int arow = tid >> 3;
    const int acol = (tid & 7) * 4;
    const int brow = tid >> 2;
    const int bcol = (tid & 3) * 8;

    for (int k0 = 0; k0 < DDIM; k0 += 32) {
#pragma unroll
        for (int p = 0; p < 4; p++) {
            int r = arow + p * 32;
            float4 v = *(const float4*)(x + (size_t)(m0 + r) * DDIM + k0 + acol);
            As[acol + 0][r] = v.x;
            As[acol + 1][r] = v.y;
            As[acol + 2][r] = v.z;
            As[acol + 3][r] = v.w;
        }
        {
            const float* wrow = Wp + (size_t)(erow0 + brow) * DDIM + k0 + bcol;
            float4 v0 = *(const float4*)(wrow);
            float4 v1 = *(const float4*)(wrow + 4);
            Bs[bcol + 0][brow] = v0.x;
            Bs[bcol + 1][brow] = v0.y;
            Bs[bcol + 2][brow] = v0.z;
            Bs[bcol + 3][brow] = v0.w;
            Bs[bcol + 4][brow] = v1.x;
            Bs[bcol + 5][brow] = v1.y;
            Bs[bcol + 6][brow] = v1.z;
            Bs[bcol + 7][brow] = v1.w;
        }
        __syncthreads();

#pragma unroll
        for (int kk = 0; kk < 32; kk++) {
            float a[8];
            float4 a0 = *(const float4*)&As[kk][ty * 8];
            float4 a1 = *(const float4*)&As[kk][ty * 8 + 4];
            a[0] = a0.x; a[1] = a0.y; a[2] = a0.z; a[3] = a0.w;
            a[4] = a1.x; a[5] = a1.y; a[6] = a1.z; a[7] = a1.w;
            float4 bv = *(const float4*)&Bs[kk][tx * 4];
            float bj[4] = {bv.x, bv.y, bv.z, bv.w};
#pragma unroll
            for (int i = 0; i < 8; i++)
#pragma unroll
                for (int j = 0; j < 4; j++)
                    acc[i][j] = fmaf(a[i], bj[j], acc[i][j]);
        }
        __syncthreads();
    }

#pragma unroll
    for (int i = 0; i < 8; i++) {
        int m = m0 + ty * 8 + i;
#pragma unroll
        for (int j = 0; j < 4; j++) {
            int el = tx * 4 + j;
            float v = acc[i][j];
            if (mode == 0) {
                g_k[(size_t)m * DDIM + erow0 + el] = v;
            } else if (mode == 1) {
                g_q[(size_t)m * DDIM + erow0 + el] = v;
            } else if (mode == 2) {
                g_wx[(size_t)m * NDIM + el] = v;
            } else {
                g_alpha[(size_t)m * NDIM + el] = sigmoid_f(v + ba[el]);
            }
        }
    }
}

// ---------------------------------------------------------------------------
// Kernel 2: per-(t,b) scalars: kq = k_t.q_t, kk2 = k_{t-1}.k_t, kqp = k_{t-1}.q_t
// ---------------------------------------------------------------------------
__global__ void __launch_bounds__(256)
kq_kernel()
{
    int warp = threadIdx.x >> 5;
    int lane = threadIdx.x & 31;
    int row = blockIdx.x * 8 + warp;
    const bool has_prev = (row >= BATCH);
    const int prow = has_prev ? (row - BATCH) : row;
    const float* kp = g_k + (size_t)row * DDIM;
    const float* qp = g_q + (size_t)row * DDIM;
    const float* pp = g_k + (size_t)prow * DDIM;
    float akq = 0.0f, akk = 0.0f, akqp = 0.0f;
#pragma unroll
    for (int i = 0; i < DDIM / 32; i++) {
        int idx = i * 32 + lane;
        float kv = kp[idx], qv = qp[idx], pv = pp[idx];
        akq  = fmaf(kv, qv, akq);
        akk  = fmaf(pv, kv, akk);
        akqp = fmaf(pv, qv, akqp);
    }
#pragma unroll
    for (int off = 16; off > 0; off >>= 1) {
        akq  += __shfl_xor_sync(0xffffffffu, akq,  off);
        akk  += __shfl_xor_sync(0xffffffffu, akk,  off);
        akqp += __shfl_xor_sync(0xffffffffu, akqp, off);
    }
    if (lane == 0) {
        g_kq[row]  = akq;
        g_kk2[row] = has_prev ? akk  : 0.0f;
        g_kqp[row] = has_prev ? akqp : 0.0f;
    }
}

// ---------------------------------------------------------------------------
// Kernel 3: pipelined sequential scan — BULK push transport.
// Same algebra/pipeline as before: at iter t each CTA publishes partials of
// G_{t+1} = (S_{t-1}.k_{t+1}, S_{t-1}.q_{t+1}); consumers reconstruct
//   Sk_t = a_{t-1}*sum(G_t) + c2_{t-1}*(k_{t-1}.k_t)
//   Sq_t = a_{t-1}*sum(Gq_t) + c2_{t-1}*(k_{t-1}.q_t)
// Transport change: partials are staged in SMEM (64 x float2 = 512 B) and
// pushed with 8 cp.async.bulk copies (one per dest CTA) instead of 512 x 8B
// st.async messages — 8 mbarrier tx updates per step instead of 512.
// recv: 4 buffers (mod-4), parity (t>>2)&1; stage: 4 slots (reuse distance
// provably >= 2 iterations via the wait chain).
// ---------------------------------------------------------------------------
__global__ void __launch_bounds__(256, 1) __cluster_dims__(8, 1, 1)
scan_kernel(const float* __restrict__ S0,
            const float* __restrict__ Wr,
            const float* __restrict__ bvec,
            float* __restrict__ outY,
            float* __restrict__ outS)
{
    __shared__ alignas(16) float2 recv[4][8][NDIM];   // [buf][src_rank][n]
    __shared__ alignas(16) float2 stage[4][NDIM];     // [slot][n] outgoing
    __shared__ float rbuf[2][NDIM];                   // tanh(Sk), double-buffered
    __shared__ alignas(8) u64 mbar[4];

    const int tid = threadIdx.x;
    const int n = tid >> 2;
    const int g = tid & 3;
    const int b = blockIdx.x >> 3;
    const int rank = blockIdx.x & 7;
    const int dbase = rank * 64 + g * 16;

    const uint32_t recv_base  = (uint32_t)__cvta_generic_to_shared(&recv[0][0][0]);
    const uint32_t stage_base = (uint32_t)__cvta_generic_to_shared(&stage[0][0]);
    const uint32_t mbar_base  = (uint32_t)__cvta_generic_to_shared(&mbar[0]);
    const uint32_t RANK_BYTES = NDIM * 8u;            // 512 B per rank-slot

    if (tid == 0) {
#pragma unroll
        for (int s = 0; s < 4; s++) mbar_init(mbar_base + s * 8, 1);
#pragma unroll
        for (int s = 0; s < 4; s++) mbar_expect_tx(mbar_base + s * 8, 8u * RANK_BYTES);
    }
    __syncthreads();
    // All peers' mbarriers + expects must exist before any push arrives.
    asm volatile("barrier.cluster.arrive.aligned;" ::: "memory");
    asm volatile("barrier.cluster.wait.aligned;" ::: "memory");

    // Persistent registers
    float S[16], Wreg[16], kc[16], kp1[16], qp1[16], kn[16], qn[16];

#pragma unroll
    for (int j = 0; j < 16; j += 4) {
        float4 v = *(const float4*)(Wr + n * NDIM + g * 16 + j);
        Wreg[j] = v.x; Wreg[j + 1] = v.y; Wreg[j + 2] = v.z; Wreg[j + 3] = v.w;
    }
    const float breg = bvec[n];

    // S0 slice; emit as S output at index 0
    {
        const float* s0p = S0 + ((size_t)b * NDIM + n) * DDIM + dbase;
        float* so = outS + ((size_t)b * NDIM + n) * DDIM + dbase;
#pragma unroll
        for (int j = 0; j < 16; j += 4) {
            float4 v = *(const float4*)(s0p + j);
            S[j] = v.x; S[j + 1] = v.y; S[j + 2] = v.z; S[j + 3] = v.w;
            *(float4*)(so + j) = v;
        }
    }

    // k_0 -> kc; q_0 -> qp1 (temporarily, for the G_0 pre-push)
    {
        const float* kp = g_k + (size_t)b * DDIM + dbase;
        const float* qp = g_q + (size_t)b * DDIM + dbase;
#pragma unroll
        for (int j = 0; j < 16; j += 4) {
            float4 vk = *(const float4*)(kp + j);
            float4 vq = *(const float4*)(qp + j);
            kc[j] = vk.x; kc[j + 1] = vk.y; kc[j + 2] = vk.z; kc[j + 3] = vk.w;
            qp1[j] = vq.x; qp1[j + 1] = vq.y; qp1[j + 2] = vq.z; qp1[j + 3] = vq.w;
        }
    }

    // Pre-push G_0 = (S0.k_0, S0.q_0) into recv buf 0, stage slot 3 ("t = -1")
    {
        float pk = 0.0f, pq = 0.0f;
#pragma unroll
        for (int j = 0; j < 16; j++) {
            pk = fmaf(S[j], kc[j], pk);
            pq = fmaf(S[j], qp1[j], pq);
        }
        pk += __shfl_xor_sync(0xffffffffu, pk, 1);
        pk += __shfl_xor_sync(0xffffffffu, pk, 2);
        pq += __shfl_xor_sync(0xffffffffu, pq, 1);
        pq += __shfl_xor_sync(0xffffffffu, pq, 2);
        if (g == 0) stage[3][n] = make_float2(pk, pq);
        __syncthreads();
        if (tid < 8) {
            fence_proxy_async_cta();
            uint32_t lsrc = stage_base + 3u * RANK_BYTES;
            uint32_t ldst = recv_base + (uint32_t)(0 * 8 + rank) * RANK_BYTES;
            uint32_t lmb  = mbar_base + 0u;
            bulk_s2s(mapa_sh(ldst, tid), lsrc, RANK_BYTES, mapa_sh(lmb, tid));
        }
    }

    // k_1 / q_1 -> kp1/qp1
    {
        const size_t row1 = (size_t)BATCH + b;
        const float* kp = g_k + row1 * DDIM + dbase;
        const float* qp = g_q + row1 * DDIM + dbase;
#pragma unroll
        for (int j = 0; j < 16; j += 4) {
            float4 vk = *(const float4*)(kp + j);
            float4 vq = *(const float4*)(qp + j);
            kp1[j] = vk.x; kp1[j + 1] = vk.y; kp1[j + 2] = vk.z; kp1[j + 3] = vk.w;
            qp1[j] = vq.x; qp1[j + 1] = vq.y; qp1[j + 2] = vq.z; qp1[j + 3] = vq.w;
        }
    }

    // Scalars for t=0
    float alc, wxc, kqc, kk2c, kqpc;
    {
        const size_t row0 = (size_t)b;
        alc  = g_alpha[row0 * NDIM + n];
        wxc  = g_wx[row0 * NDIM + n];
        kqc  = g_kq[row0];
        kk2c = g_kk2[row0];   // = 0
        kqpc = g_kqp[row0];   // = 0
    }

    float a_prev = 1.0f, c2_prev = 0.0f;

    for (int t = 0; t < T_STEPS; t++) {
        const int sslot = t & 3;

        // 1) partial dots for G_{t+1} from S (= S_{t-1}), k_{t+1}, q_{t+1};
        //    stage locally (g==0 writes 8B per n)
        {
            float pk = 0.0f, pq = 0.0f;
#pragma unroll
            for (int j = 0; j < 16; j++) {
                pk = fmaf(S[j], kp1[j], pk);
                pq = fmaf(S[j], qp1[j], pq);
            }
            pk += __shfl_xor_sync(0xffffffffu, pk, 1);
            pk += __shfl_xor_sync(0xffffffffu, pk, 2);
            pq += __shfl_xor_sync(0xffffffffu, pq, 1);
            pq += __shfl_xor_sync(0xffffffffu, pq, 2);
            if (g == 0) stage[sslot][n] = make_float2(pk, pq);
        }
        __syncthreads();   // stage visible CTA-wide

        // 2) bulk-push the staged 512B vector to all 8 ranks (warp 0 lanes)
        if (t + 1 < T_STEPS && tid < 8) {
            const int dbuf = (t + 1) & 3;
            fence_proxy_async_cta();
            uint32_t lsrc = stage_base + (uint32_t)sslot * RANK_BYTES;
            uint32_t ldst = recv_base + (uint32_t)(dbuf * 8 + rank) * RANK_BYTES;
            uint32_t lmb  = mbar_base + (uint32_t)(dbuf * 8);
            bulk_s2s(mapa_sh(ldst, tid), lsrc, RANK_BYTES, mapa_sh(lmb, tid));
        }

        // 3) prefetch k/q for t+2 and scalars for t+1 (clamped)
        float wxn, aln, kqn, kk2n, kqpn;
        {
            const int t2 = (t + 2 < T_STEPS) ? (t + 2) : (T_STEPS - 1);
            const size_t row2 = (size_t)t2 * BATCH + b;
            const float* kp = g_k + row2 * DDIM + dbase;
            const float* qp = g_q + row2 * DDIM + dbase;
#pragma unroll
            for (int j = 0; j < 16; j += 4) {
                float4 vk = *(const float4*)(kp + j);
                float4 vq = *(const float4*)(qp + j);
                kn[j] = vk.x; kn[j + 1] = vk.y; kn[j + 2] = vk.z; kn[j + 3] = vk.w;
                qn[j] = vq.x; qn[j + 1] = vq.y; qn[j + 2] = vq.z; qn[j + 3] = vq.w;
            }
            const int t1 = (t + 1 < T_STEPS) ? (t + 1) : (T_STEPS - 1);
            const size_t row1 = (size_t)t1 * BATCH + b;
            aln  = g_alpha[row1 * NDIM + n];
            wxn  = g_wx[row1 * NDIM + n];
            kqn  = g_kq[row1];
            kk2n = g_kk2[row1];
            kqpn = g_kqp[row1];
        }

        // 4) wait for step t's gather; re-arm this mbarrier for step t+4
        const int wbuf = t & 3;
        const uint32_t parity = (uint32_t)((t >> 2) & 1);
        mbar_wait_parity(mbar_base + (uint32_t)(wbuf * 8), parity);
        if (tid == 0) mbar_expect_tx(mbar_base + (uint32_t)(wbuf * 8), 8u * RANK_BYTES);

        // 5) sum 8 rank-partials + one-step correction
        float2 p1 = recv[wbuf][2 * g + 0][n];
        float2 p2 = recv[wbuf][2 * g + 1][n];
        float skG = p1.x + p2.x;
        float sqG = p1.y + p2.y;
        skG += __shfl_xor_sync(0xffffffffu, skG, 1);
        skG += __shfl_xor_sync(0xffffffffu, skG, 2);
        sqG += __shfl_xor_sync(0xffffffffu, sqG, 1);
        sqG += __shfl_xor_sync(0xffffffffu, sqG, 2);
        const float sk = fmaf(a_prev, skG, c2_prev * kk2c);
        const float sq = fmaf(a_prev, sqG, c2_prev * kqpc);

        // 6) retrieved = tanh(Sk); broadcast; W_r matvec
        const int rb = t & 1;
        float rn = tanh_f(sk);
        if (g == 0) rbuf[rb][n] = rn;
        __syncthreads();

        float accv = 0.0f;
        {
            const float* rp = &rbuf[rb][g * 16];
#pragma unroll
            for (int j = 0; j < 16; j++)
                accv = fmaf(Wreg[j], rp[j], accv);
        }
        accv += __shfl_xor_sync(0xffffffffu, accv, 1);
        accv += __shfl_xor_sync(0xffffffffu, accv, 2);

        const float v  = tanh_f(accv + wxc + breg);
        const float al = alc;
        const float c2 = (1.0f - al) * v;

        // 7) state update + store S_{t+1}
#pragma unroll
        for (int j = 0; j < 16; j++)
            S[j] = fmaf(al, S[j], c2 * kc[j]);
        {
            float* sp = outS + (((size_t)(t + 1) * BATCH + b) * NDIM + n) * DDIM + dbase;
#pragma unroll
            for (int j = 0; j < 16; j += 4)
                *(float4*)(sp + j) = make_float4(S[j], S[j + 1], S[j + 2], S[j + 3]);
        }

        // 8) y_t = tanh(al*Sq_t + c2*(k_t.q_t))
        if (g == 0) {
            float y = tanh_f(fmaf(al, sq, c2 * kqc));
            outY[((size_t)t * BATCH + b) * NDIM + n] = y;
        }

        // 9) rotate pipeline registers / scalars
        a_prev = al; c2_prev = c2;
#pragma unroll
        for (int j = 0; j < 16; j++) { kc[j] = kp1[j]; kp1[j] = kn[j]; qp1[j] = qn[j]; }
        alc = aln; wxc = wxn; kqc = kqn; kk2c = kk2n; kqpc = kqpn;
    }

    __syncthreads();
    asm volatile("barrier.cluster.arrive.aligned;" ::: "memory");
    asm volatile("barrier.cluster.wait.aligned;" ::: "memory");
}

// ---------------------------------------------------------------------------
// Launch
// Inputs (metadata order): x, S0, W_k, W_q, W_x, W_r, b, W_alpha, b_alpha
// Output: concat(output [T,B,N], S [T+1,B,N,D]) as float32
// ---------------------------------------------------------------------------
extern "C" void kernel_launch(void* const* d_in, const int* in_sizes, int n_in,
                              void* d_out, int out_size)
{
    const float* x   = (const float*)d_in[0];
    const float* S0  = (const float*)d_in[1];
    const float* Wk  = (const float*)d_in[2];
    const float* Wq  = (const float*)d_in[3];
    const float* Wx  = (const float*)d_in[4];
    const float* Wrm = (const float*)d_in[5];
    const float* bv  = (const float*)d_in[6];
    const float* Wa  = (const float*)d_in[7];
    const float* ba  = (const float*)d_in[8];

    float* outY = (float*)d_out;
    float* outS = outY + (size_t)T_STEPS * BATCH * NDIM;

    dim3 gemm_grid(M_ROWS / 128, E_COLS / 64);  // (32, 18)
    proj_gemm_kernel<<<gemm_grid, 256>>>(x, Wk, Wq, Wx, Wa, ba);
    kq_kernel<<<M_ROWS / 8, 256>>>();
    scan_kernel<<<64, 256>>>(S0, Wrm, bv, outY, outS);
}

// round 16
// speedup vs baseline: 1.6535x; 1.6535x over previous
#include <cuda_runtime.h>
#include <cstdint>

// Problem constants
#define T_STEPS 512
#define BATCH   8
#define DDIM    512
#define NDIM    64
#define M_ROWS  (T_STEPS * BATCH)   // 4096 rows for the projection GEMM
#define E_COLS  1152                // 512 (k) + 512 (q) + 64 (wx) + 64 (alpha)

typedef unsigned long long u64;

// ---------------------------------------------------------------------------
// Scratch (no cudaMalloc allowed)
// ---------------------------------------------------------------------------
__device__ float g_k[M_ROWS * DDIM];      // k_all   [T*B, D]
__device__ float g_q[M_ROWS * DDIM];      // q_all   [T*B, D]
__device__ float g_wx[M_ROWS * NDIM];     // Wx_all  [T*B, N]
__device__ float g_alpha[M_ROWS * NDIM];  // sigmoid(ax_all) [T*B, N]
__device__ float g_kq[M_ROWS];            // k_t . q_t
__device__ float g_kk2[M_ROWS];           // k_{t-1} . k_t   (0 at t=0)
__device__ float g_kqp[M_ROWS];           // k_{t-1} . q_t   (0 at t=0)

// ---------------------------------------------------------------------------
// Fast math helpers
// ---------------------------------------------------------------------------
__device__ __forceinline__ float tanh_f(float x) {
    float e = __expf(2.0f * x);
    return 1.0f - __fdividef(2.0f, e + 1.0f);
}
__device__ __forceinline__ float sigmoid_f(float x) {
    float e = __expf(-x);
    return __fdividef(1.0f, 1.0f + e);
}

// ---------------------------------------------------------------------------
// Cluster / mbarrier helpers
// ---------------------------------------------------------------------------
__device__ __forceinline__ uint32_t mapa_sh(uint32_t addr, int rank) {
    uint32_t d;
    asm("mapa.shared::cluster.u32 %0, %1, %2;" : "=r"(d) : "r"(addr), "r"(rank));
    return d;
}
__device__ __forceinline__ void mbar_init(uint32_t addr, uint32_t cnt) {
    asm volatile("mbarrier.init.shared.b64 [%0], %1;" :: "r"(addr), "r"(cnt) : "memory");
}
__device__ __forceinline__ void mbar_expect_tx(uint32_t addr, uint32_t bytes) {
    asm volatile("mbarrier.arrive.expect_tx.shared.b64 _, [%0], %1;"
                 :: "r"(addr), "r"(bytes) : "memory");
}
__device__ __forceinline__ void mbar_wait_parity(uint32_t addr, uint32_t parity) {
    asm volatile(
        "{\n\t"
        ".reg .pred P;\n\t"
        "WAIT_%=:\n\t"
        "mbarrier.try_wait.parity.acquire.cluster.shared::cta.b64 P, [%0], %1, 0x989680;\n\t"
        "@!P bra WAIT_%=;\n\t"
        "}"
        :: "r"(addr), "r"(parity) : "memory");
}
__device__ __forceinline__ void st_async_b64(uint32_t raddr, u64 val, uint32_t rmbar) {
    asm volatile("st.async.shared::cluster.mbarrier::complete_tx::bytes.b64 [%0], %1, [%2];"
                 :: "r"(raddr), "l"(val), "r"(rmbar) : "memory");
}
__device__ __forceinline__ void st_async_b32(uint32_t raddr, uint32_t val, uint32_t rmbar) {
    asm volatile("st.async.shared::cluster.mbarrier::complete_tx::bytes.b32 [%0], %1, [%2];"
                 :: "r"(raddr), "r"(val), "r"(rmbar) : "memory");
}
__device__ __forceinline__ u64 pack_f2(float lo, float hi) {
    u64 r;
    asm("mov.b64 %0, {%1, %2};" : "=l"(r) : "f"(lo), "f"(hi));
    return r;
}

// ---------------------------------------------------------------------------
// Kernel 1: fused projection GEMM (unchanged; ~125 us)
// ---------------------------------------------------------------------------
__global__ void __launch_bounds__(256)
proj_gemm_kernel(const float* __restrict__ x,
                 const float* __restrict__ Wk,
                 const float* __restrict__ Wq,
                 const float* __restrict__ Wx,
                 const float* __restrict__ Wa,
                 const float* __restrict__ ba)
{
    __shared__ float As[32][132];
    __shared__ float Bs[32][68];

    const int tid = threadIdx.x;
    const int m0 = blockIdx.x * 128;
    const int etile = blockIdx.y;

    const float* Wp;
    int erow0, mode;
    if (etile < 8)        { Wp = Wk; erow0 = etile * 64;        mode = 0; }
    else if (etile < 16)  { Wp = Wq; erow0 = (etile - 8) * 64;  mode = 1; }
    else if (etile == 16) { Wp = Wx; erow0 = 0;                 mode = 2; }
    else                  { Wp = Wa; erow0 = 0;                 mode = 3; }

    const int tx = tid & 15;
    const int ty = tid >> 4;

    float acc[8][4];
#pragma unroll
    for (int i = 0; i < 8; i++)
#pragma unroll
        for (int j = 0; j < 4; j++) acc[i][j] = 0.0f;

    const int arow = tid >> 3;
    const int acol = (tid & 7) * 4;
    const int brow = tid >> 2;
    const int bcol = (tid & 3) * 8;

    for (int k0 = 0; k0 < DDIM; k0 += 32) {
#pragma unroll
        for (int p = 0; p < 4; p++) {
            int r = arow + p * 32;
            float4 v = *(const float4*)(x + (size_t)(m0 + r) * DDIM + k0 + acol);
            As[acol + 0][r] = v.x;
            As[acol + 1][r] = v.y;
            As[acol + 2][r] = v.z;
            As[acol + 3][r] = v.w;
        }
        {
            const float* wrow = Wp + (size_t)(erow0 + brow) * DDIM + k0 + bcol;
            float4 v0 = *(const float4*)(wrow);
            float4 v1 = *(const float4*)(wrow + 4);
            Bs[bcol + 0][brow] = v0.x;
            Bs[bcol + 1][brow] = v0.y;
            Bs[bcol + 2][brow] = v0.z;
            Bs[bcol + 3][brow] = v0.w;
            Bs[bcol + 4][brow] = v1.x;
            Bs[bcol + 5][brow] = v1.y;
            Bs[bcol + 6][brow] = v1.z;
            Bs[bcol + 7][brow] = v1.w;
        }
        __syncthreads();

#pragma unroll
        for (int kk = 0; kk < 32; kk++) {
            float a[8];
            float4 a0 = *(const float4*)&As[kk][ty * 8];
            float4 a1 = *(const float4*)&As[kk][ty * 8 + 4];
            a[0] = a0.x; a[1] = a0.y; a[2] = a0.z; a[3] = a0.w;
            a[4] = a1.x; a[5] = a1.y; a[6] = a1.z; a[7] = a1.w;
            float4 bv = *(const float4*)&Bs[kk][tx * 4];
            float bj[4] = {bv.x, bv.y, bv.z, bv.w};
#pragma unroll
            for (int i = 0; i < 8; i++)
#pragma unroll
                for (int j = 0; j < 4; j++)
                    acc[i][j] = fmaf(a[i], bj[j], acc[i][j]);
        }
        __syncthreads();
    }

#pragma unroll
    for (int i = 0; i < 8; i++) {
        int m = m0 + ty * 8 + i;
#pragma unroll
        for (int j = 0; j < 4; j++) {
            int el = tx * 4 + j;
            float v = acc[i][j];
            if (mode == 0) {
                g_k[(size_t)m * DDIM + erow0 + el] = v;
            } else if (mode == 1) {
                g_q[(size_t)m * DDIM + erow0 + el] = v;
            } else if (mode == 2) {
                g_wx[(size_t)m * NDIM + el] = v;
            } else {
                g_alpha[(size_t)m * NDIM + el] = sigmoid_f(v + ba[el]);
            }
        }
    }
}

// ---------------------------------------------------------------------------
// Kernel 2: per-(t,b) scalars: kq = k_t.q_t, kk2 = k_{t-1}.k_t, kqp = k_{t-1}.q_t
// ---------------------------------------------------------------------------
__global__ void __launch_bounds__(256)
kq_kernel()
{
    int warp = threadIdx.x >> 5;
    int lane = threadIdx.x & 31;
    int row = blockIdx.x * 8 + warp;
    const bool has_prev = (row >= BATCH);
    const int prow = has_prev ? (row - BATCH) : row;
    const float* kp = g_k + (size_t)row * DDIM;
    const float* qp = g_q + (size_t)row * DDIM;
    const float* pp = g_k + (size_t)prow * DDIM;
    float akq = 0.0f, akk = 0.0f, akqp = 0.0f;
#pragma unroll
    for (int i = 0; i < DDIM / 32; i++) {
        int idx = i * 32 + lane;
        float kv = kp[idx], qv = qp[idx], pv = pp[idx];
        akq  = fmaf(kv, qv, akq);
        akk  = fmaf(pv, kv, akk);
        akqp = fmaf(pv, qv, akqp);
    }
#pragma unroll
    for (int off = 16; off > 0; off >>= 1) {
        akq  += __shfl_xor_sync(0xffffffffu, akq,  off);
        akk  += __shfl_xor_sync(0xffffffffu, akk,  off);
        akqp += __shfl_xor_sync(0xffffffffu, akqp, off);
    }
    if (lane == 0) {
        g_kq[row]  = akq;
        g_kk2[row] = has_prev ? akk  : 0.0f;
        g_kqp[row] = has_prev ? akqp : 0.0f;
    }
}

// ---------------------------------------------------------------------------
// Kernel 3: reduce-scatter + broadcast pipelined scan.
// Cluster of 8 CTAs per batch; CTA rank owns n-group [rank*8, rank*8+8)
// (handled by warp `rank` in every CTA — group-w traffic is warp-w only).
//
// Iter t (r_t already broadcast):
//   1. prefetch k/q row t+2, scalars
//   2. wait(B, t)  -> r_t vector local        [pushed by owners, iter t-1]
//   3. matvec v_t = tanh(Wr.r_t + wx + b); al_t; c2_t
//   4. owner: y_t = tanh(al_t*sq_t + c2_t*kq_t)   (sq_t from iter t-1)
//   5. S = al_t*S + c2_t*k_t ; store S_{t+1}
//   6. dots G_{t+2} = (S_t.k_{t+2}, S_t.q_{t+2}); one 8B st.async per n
//      to the OWNER rank only (reduce-scatter)          [64 msgs/CTA]
//   7. owner: wait(A, t+1) -> sum 8 partials;
//      Sk_{t+1} = al_t*SumG + c2_t*(k_t.k_{t+1});  sq_{t+1} likewise;
//      r_{t+1} = tanh(Sk); broadcast 4B to all ranks    [64 msgs/CTA]
//   8. __syncthreads (bounds intra-CTA warp skew); rotate registers
//
// recv bufs: 4-deep mod-4, parity (step>>2)&1. Per-CTA drain: 128 msgs/step
// (vs 512 in the all-to-all scheme).
// ---------------------------------------------------------------------------
__global__ void __launch_bounds__(256, 1) __cluster_dims__(8, 1, 1)
scan_kernel(const float* __restrict__ S0,
            const float* __restrict__ Wr,
            const float* __restrict__ bvec,
            float* __restrict__ outY,
            float* __restrict__ outS)
{
    __shared__ alignas(16) float2 recvA[4][8][8];   // [buf][src_rank][n_local]
    __shared__ alignas(16) float  recvB[4][NDIM];   // [buf][n] broadcast r
    __shared__ alignas(8) u64 mbarA[4];
    __shared__ alignas(8) u64 mbarB[4];

    const int tid  = threadIdx.x;
    const int wid  = tid >> 5;          // warp = n-group
    const int n    = tid >> 2;
    const int g    = tid & 3;
    const int b    = blockIdx.x >> 3;
    const int rank = blockIdx.x & 7;
    const int dbase = rank * 64 + g * 16;
    const int nl   = n & 7;             // n_local within group
    const bool is_owner = (wid == rank);

    const uint32_t recvA_base = (uint32_t)__cvta_generic_to_shared(&recvA[0][0][0]);
    const uint32_t recvB_base = (uint32_t)__cvta_generic_to_shared(&recvB[0][0]);
    const uint32_t mbarA_base = (uint32_t)__cvta_generic_to_shared(&mbarA[0]);
    const uint32_t mbarB_base = (uint32_t)__cvta_generic_to_shared(&mbarB[0]);
    const uint32_t A_TX = 8u * 8u * 8u;   // 512 B  (8 ranks x 8 n_local x 8B)
    const uint32_t B_TX = 64u * 4u;       // 256 B  (8 owners x 8 n x 4B)

    if (tid == 0) {
#pragma unroll
        for (int s = 0; s < 4; s++) {
            mbar_init(mbarA_base + s * 8, 1);
            mbar_init(mbarB_base + s * 8, 1);
        }
#pragma unroll
        for (int s = 0; s < 4; s++) {
            mbar_expect_tx(mbarA_base + s * 8, A_TX);
            mbar_expect_tx(mbarB_base + s * 8, B_TX);
        }
    }
    __syncthreads();
    asm volatile("barrier.cluster.arrive.aligned;" ::: "memory");
    asm volatile("barrier.cluster.wait.aligned;" ::: "memory");

    // Persistent registers
    float S[16], Wreg[16], kc[16], kp1[16], kn[16], qn[16];

#pragma unroll
    for (int j = 0; j < 16; j += 4) {
        float4 v = *(const float4*)(Wr + n * NDIM + g * 16 + j);
        Wreg[j] = v.x; Wreg[j + 1] = v.y; Wreg[j + 2] = v.z; Wreg[j + 3] = v.w;
    }
    const float breg = bvec[n];

    // S0 slice; emit as S output at index 0
    {
        const float* s0p = S0 + ((size_t)b * NDIM + n) * DDIM + dbase;
        float* so = outS + ((size_t)b * NDIM + n) * DDIM + dbase;
#pragma unroll
        for (int j = 0; j < 16; j += 4) {
            float4 v = *(const float4*)(s0p + j);
            S[j] = v.x; S[j + 1] = v.y; S[j + 2] = v.z; S[j + 3] = v.w;
            *(float4*)(so + j) = v;
        }
    }

    // k_0 -> kc, k_1 -> kp1
    {
        const float* kp0 = g_k + (size_t)b * DDIM + dbase;
        const float* kp1p = g_k + ((size_t)BATCH + b) * DDIM + dbase;
#pragma unroll
        for (int j = 0; j < 16; j += 4) {
            float4 v0 = *(const float4*)(kp0 + j);
            float4 v1 = *(const float4*)(kp1p + j);
            kc[j]  = v0.x; kc[j + 1]  = v0.y; kc[j + 2]  = v0.z; kc[j + 3]  = v0.w;
            kp1[j] = v1.x; kp1[j + 1] = v1.y; kp1[j + 2] = v1.z; kp1[j + 3] = v1.w;
        }
    }

    // Pre-push A0 = (S0.k_0, S0.q_0) and A1 = (S0.k_1, S0.q_1) to owners
    {
        const float* qp0 = g_q + (size_t)b * DDIM + dbase;
        const float* qp1 = g_q + ((size_t)BATCH + b) * DDIM + dbase;
        float q0[16], q1[16];
#pragma unroll
        for (int j = 0; j < 16; j += 4) {
            float4 v0 = *(const float4*)(qp0 + j);
            float4 v1 = *(const float4*)(qp1 + j);
            q0[j] = v0.x; q0[j + 1] = v0.y; q0[j + 2] = v0.z; q0[j + 3] = v0.w;
            q1[j] = v1.x; q1[j + 1] = v1.y; q1[j + 2] = v1.z; q1[j + 3] = v1.w;
        }
#pragma unroll
        for (int s = 0; s < 2; s++) {
            float pk = 0.0f, pq = 0.0f;
#pragma unroll
            for (int j = 0; j < 16; j++) {
                pk = fmaf(S[j], (s == 0) ? kc[j] : kp1[j], pk);
                pq = fmaf(S[j], (s == 0) ? q0[j] : q1[j], pq);
            }
            pk += __shfl_xor_sync(0xffffffffu, pk, 1);
            pk += __shfl_xor_sync(0xffffffffu, pk, 2);
            pq += __shfl_xor_sync(0xffffffffu, pq, 1);
            pq += __shfl_xor_sync(0xffffffffu, pq, 2);
            if (g == 0) {
                uint32_t la = recvA_base + (uint32_t)(((s * 8 + rank) * 8 + nl) * 8);
                uint32_t lm = mbarA_base + (uint32_t)(s * 8);
                st_async_b64(mapa_sh(la, wid), pack_f2(pk, pq), mapa_sh(lm, wid));
            }
        }
    }

    // Scalars for t=0 (current) and rows 1 (owner correction)
    float alc, wxc, kqc, kk2c, kqpc;
    {
        const size_t row0 = (size_t)b;
        const size_t row1 = (size_t)BATCH + b;
        alc  = g_alpha[row0 * NDIM + n];
        wxc  = g_wx[row0 * NDIM + n];
        kqc  = g_kq[row0];
        kk2c = g_kk2[row1];
        kqpc = g_kqp[row1];
    }

    // Owner pre-step: consume A0 -> r_0 broadcast; sq_pend = S0.q_0
    float sq_pend = 0.0f;
    if (is_owner) {
        mbar_wait_parity(mbarA_base + 0, 0);
        if ((tid & 31) == 0) mbar_expect_tx(mbarA_base + 0, A_TX);
        float2 a1 = recvA[0][2 * g + 0][nl];
        float2 a2 = recvA[0][2 * g + 1][nl];
        float sk = a1.x + a2.x;
        float sq = a1.y + a2.y;
        sk += __shfl_xor_sync(0xffffffffu, sk, 1);
        sk += __shfl_xor_sync(0xffffffffu, sk, 2);
        sq += __shfl_xor_sync(0xffffffffu, sq, 1);
        sq += __shfl_xor_sync(0xffffffffu, sq, 2);
        sq_pend = sq;                       // Sq for step 0 (a=1, c2=0)
        float r0 = tanh_f(sk);              // Sk_0 = S0.k_0 exactly
        uint32_t la = recvB_base + (uint32_t)((0 * NDIM + n) * 4);
        uint32_t lm = mbarB_base + 0;
        st_async_b32(mapa_sh(la, 2 * g + 0), __float_as_uint(r0), mapa_sh(lm, 2 * g + 0));
        st_async_b32(mapa_sh(la, 2 * g + 1), __float_as_uint(r0), mapa_sh(lm, 2 * g + 1));
    }

    for (int t = 0; t < T_STEPS; t++) {
        const int bufT  = t & 3;
        const uint32_t parT = (uint32_t)((t >> 2) & 1);

        // 1) prefetch k/q row t+2 and scalars (row t+1 current-next, row t+2 corr-next)
        float aln, wxn, kqn, kk2n, kqpn;
        {
            const int t2 = (t + 2 < T_STEPS) ? (t + 2) : (T_STEPS - 1);
            const size_t row2 = (size_t)t2 * BATCH + b;
            const float* kp = g_k + row2 * DDIM + dbase;
            const float* qp = g_q + row2 * DDIM + dbase;
#pragma unroll
            for (int j = 0; j < 16; j += 4) {
                float4 vk = *(const float4*)(kp + j);
                float4 vq = *(const float4*)(qp + j);
                kn[j] = vk.x; kn[j + 1] = vk.y; kn[j + 2] = vk.z; kn[j + 3] = vk.w;
                qn[j] = vq.x; qn[j + 1] = vq.y; qn[j + 2] = vq.z; qn[j + 3] = vq.w;
            }
            const int t1 = (t + 1 < T_STEPS) ? (t + 1) : (T_STEPS - 1);
            const size_t row1 = (size_t)t1 * BATCH + b;
            aln  = g_alpha[row1 * NDIM + n];
            wxn  = g_wx[row1 * NDIM + n];
            kqn  = g_kq[row1];
            kk2n = g_kk2[row2];
            kqpn = g_kqp[row2];
        }

        // 2) wait for r_t broadcast; re-arm
        mbar_wait_parity(mbarB_base + (uint32_t)(bufT * 8), parT);
        if (tid == 0) mbar_expect_tx(mbarB_base + (uint32_t)(bufT * 8), B_TX);

        // 3) matvec v_t = tanh(Wr.r_t + wx + b)
        float accv = 0.0f;
        {
            const float* rp = &recvB[bufT][g * 16];
#pragma unroll
            for (int j = 0; j < 16; j++)
                accv = fmaf(Wreg[j], rp[j], accv);
        }
        accv += __shfl_xor_sync(0xffffffffu, accv, 1);
        accv += __shfl_xor_sync(0xffffffffu, accv, 2);

        const float v  = tanh_f(accv + wxc + breg);
        const float al = alc;
        const float c2 = (1.0f - al) * v;

        // 4) owner: y_t = tanh(al_t*Sq_t + c2_t*(k_t.q_t))
        if (is_owner && g == 0) {
            float y = tanh_f(fmaf(al, sq_pend, c2 * kqc));
            outY[((size_t)t * BATCH + b) * NDIM + n] = y;
        }

        // 5) state update + store S_{t+1}
#pragma unroll
        for (int j = 0; j < 16; j++)
            S[j] = fmaf(al, S[j], c2 * kc[j]);
        {
            float* sp = outS + (((size_t)(t + 1) * BATCH + b) * NDIM + n) * DDIM + dbase;
#pragma unroll
            for (int j = 0; j < 16; j += 4)
                *(float4*)(sp + j) = make_float4(S[j], S[j + 1], S[j + 2], S[j + 3]);
        }

        // 6) dots G_{t+2} = (S_t.k_{t+2}, S_t.q_{t+2}); reduce-scatter to owner
        if (t + 2 < T_STEPS) {
            float pk = 0.0f, pq = 0.0f;
#pragma unroll
            for (int j = 0; j < 16; j++) {
                pk = fmaf(S[j], kn[j], pk);
                pq = fmaf(S[j], qn[j], pq);
            }
            pk += __shfl_xor_sync(0xffffffffu, pk, 1);
            pk += __shfl_xor_sync(0xffffffffu, pk, 2);
            pq += __shfl_xor_sync(0xffffffffu, pq, 1);
            pq += __shfl_xor_sync(0xffffffffu, pq, 2);
            if (g == 0) {
                const int dbuf = (t + 2) & 3;
                uint32_t la = recvA_base + (uint32_t)(((dbuf * 8 + rank) * 8 + nl) * 8);
                uint32_t lm = mbarA_base + (uint32_t)(dbuf * 8);
                st_async_b64(mapa_sh(la, wid), pack_f2(pk, pq), mapa_sh(lm, wid));
            }
        }

        // 7) owner: consume A(t+1) -> r_{t+1}; broadcast
        if (is_owner && (t + 1 < T_STEPS)) {
            const int abuf = (t + 1) & 3;
            const uint32_t apar = (uint32_t)(((t + 1) >> 2) & 1);
            mbar_wait_parity(mbarA_base + (uint32_t)(abuf * 8), apar);
            if ((tid & 31) == 0) mbar_expect_tx(mbarA_base + (uint32_t)(abuf * 8), A_TX);
            float2 a1 = recvA[abuf][2 * g + 0][nl];
            float2 a2 = recvA[abuf][2 * g + 1][nl];
            float sk = a1.x + a2.x;
            float sq = a1.y + a2.y;
            sk += __shfl_xor_sync(0xffffffffu, sk, 1);
            sk += __shfl_xor_sync(0xffffffffu, sk, 2);
            sq += __shfl_xor_sync(0xffffffffu, sq, 1);
            sq += __shfl_xor_sync(0xffffffffu, sq, 2);
            // one-step correction: Sk_{t+1} = al_t*SumG + c2_t*(k_t.k_{t+1})
            sk = fmaf(al, sk, c2 * kk2c);
            sq_pend = fmaf(al, sq, c2 * kqpc);
            float rn = tanh_f(sk);
            uint32_t la = recvB_base + (uint32_t)((abuf * NDIM + n) * 4);
            uint32_t lm = mbarB_base + (uint32_t)(abuf * 8);
            st_async_b32(mapa_sh(la, 2 * g + 0), __float_as_uint(rn), mapa_sh(lm, 2 * g + 0));
            st_async_b32(mapa_sh(la, 2 * g + 1), __float_as_uint(rn), mapa_sh(lm, 2 * g + 1));
        }

        // 8) bound intra-CTA warp skew; rotate registers
        __syncthreads();
#pragma unroll
        for (int j = 0; j < 16; j++) { kc[j] = kp1[j]; kp1[j] = kn[j]; }
        alc = aln; wxc = wxn; kqc = kqn; kk2c = kk2n; kqpc = kqpn;
    }

    __syncthreads();
    asm volatile("barrier.cluster.arrive.aligned;" ::: "memory");
    asm volatile("barrier.cluster.wait.aligned;" ::: "memory");
}

// ---------------------------------------------------------------------------
// Launch
// Inputs (metadata order): x, S0, W_k, W_q, W_x, W_r, b, W_alpha, b_alpha
// Output: concat(output [T,B,N], S [T+1,B,N,D]) as float32
// ---------------------------------------------------------------------------
extern "C" void kernel_launch(void* const* d_in, const int* in_sizes, int n_in,
                              void* d_out, int out_size)
{
    const float* x   = (const float*)d_in[0];
    const float* S0  = (const float*)d_in[1];
    const float* Wk  = (const float*)d_in[2];
    const float* Wq  = (const float*)d_in[3];
    const float* Wx  = (const float*)d_in[4];
    const float* Wrm = (const float*)d_in[5];
    const float* bv  = (const float*)d_in[6];
    const float* Wa  = (const float*)d_in[7];
    const float* ba  = (const float*)d_in[8];

    float* outY = (float*)d_out;
    float* outS = outY + (size_t)T_STEPS * BATCH * NDIM;

    dim3 gemm_grid(M_ROWS / 128, E_COLS / 64);  // (32, 18)
    proj_gemm_kernel<<<gemm_grid, 256>>>(x, Wk, Wq, Wx, Wa, ba);
    kq_kernel<<<M_ROWS / 8, 256>>>();
    scan_kernel<<<64, 256>>>(S0, Wrm, bv, outY, outS);
}